// round 1
// baseline (speedup 1.0000x reference)
#include <cuda_runtime.h>
#include <cstdint>

#define B_  2
#define L_  2048
#define DM  1024
#define NH  16
#define DQ  64

// Scratch (allocation-free rule: __device__ globals)
__device__ float g_q[(size_t)B_ * NH * L_ * DQ];
__device__ float g_k[(size_t)B_ * NH * L_ * DQ];
__device__ float g_v[(size_t)B_ * NH * L_ * DQ];
__device__ float g_o[(size_t)B_ * NH * L_ * DQ];
__device__ float g_y[(size_t)B_ * L_ * DM];

// ---------------------------------------------------------------------------
// Kernel 1: fused QKV projection.
// q[b,h,l,e] = sum_d x[b,l,d] * w[h,d,e]    (blockIdx.z selects q/k/v)
// GEMM per (h, z): M = B*L = 4096, N = 64, K = 1024.
// Tile 64x64, BK=16, 256 threads, 4x4 register micro-tile.
// ---------------------------------------------------------------------------
__global__ __launch_bounds__(256) void qkv_proj_kernel(
    const float* __restrict__ X,
    const float* __restrict__ Wq,
    const float* __restrict__ Wk,
    const float* __restrict__ Wv)
{
    const float* W;
    float* O;
    if (blockIdx.z == 0)      { W = Wq; O = g_q; }
    else if (blockIdx.z == 1) { W = Wk; O = g_k; }
    else                      { W = Wv; O = g_v; }

    const int h  = blockIdx.y;
    const int m0 = blockIdx.x * 64;

    __shared__ float Xs[16][68];   // transposed X tile, padded (16B-aligned rows)
    __shared__ float Ws[16][64];

    const int tid = threadIdx.x;
    const int tx  = tid & 15;        // output col group (e)
    const int ty  = tid >> 4;        // output row group
    const int lr  = tid >> 2;        // load row in X tile
    const int lc  = (tid & 3) << 2;  // load col in X tile

    const float* Wh = W + (size_t)h * DM * DQ;

    float acc[4][4];
#pragma unroll
    for (int i = 0; i < 4; i++)
#pragma unroll
        for (int j = 0; j < 4; j++) acc[i][j] = 0.f;

    for (int k0 = 0; k0 < DM; k0 += 16) {
        float4 xv = *(const float4*)(X + (size_t)(m0 + lr) * DM + k0 + lc);
        Xs[lc + 0][lr] = xv.x;
        Xs[lc + 1][lr] = xv.y;
        Xs[lc + 2][lr] = xv.z;
        Xs[lc + 3][lr] = xv.w;
        *(float4*)&Ws[ty][tx << 2] =
            *(const float4*)(Wh + (size_t)(k0 + ty) * DQ + (tx << 2));
        __syncthreads();

#pragma unroll
        for (int kk = 0; kk < 16; kk++) {
            float4 a = *(float4*)&Xs[kk][ty << 2];
            float4 b = *(float4*)&Ws[kk][tx << 2];
            float av[4] = {a.x, a.y, a.z, a.w};
            float bv[4] = {b.x, b.y, b.z, b.w};
#pragma unroll
            for (int i = 0; i < 4; i++)
#pragma unroll
                for (int j = 0; j < 4; j++) acc[i][j] += av[i] * bv[j];
        }
        __syncthreads();
    }

#pragma unroll
    for (int i = 0; i < 4; i++) {
        int row = m0 + (ty << 2) + i;
        int bb  = row >> 11;          // row / L_
        int l   = row & (L_ - 1);
        float4 v = make_float4(acc[i][0], acc[i][1], acc[i][2], acc[i][3]);
        *(float4*)(O + ((((size_t)bb * NH + h) * L_ + l) << 6) + (tx << 2)) = v;
    }
}

// ---------------------------------------------------------------------------
// Kernel 2: attention per (b, h). One thread = one query row (q, o in regs).
// Flash-style online softmax over key tiles of 64, K/V tiles in smem.
// ---------------------------------------------------------------------------
__global__ __launch_bounds__(128) void attn_kernel(const uint8_t* __restrict__ mask)
{
    const int h  = blockIdx.y;
    const int bb = blockIdx.z;
    const int r  = blockIdx.x * 128 + threadIdx.x;   // query row in [0, L)
    const size_t bh = (size_t)bb * NH + h;

    __shared__ float Ks[64][64];
    __shared__ float Vs[64][64];

    const float* Q = g_q + ((bh * L_ + r) << 6);
    float q[64], o[64];
#pragma unroll
    for (int e4 = 0; e4 < 16; e4++) {
        float4 t = *(const float4*)(Q + (e4 << 2));
        q[e4 * 4 + 0] = t.x; q[e4 * 4 + 1] = t.y;
        q[e4 * 4 + 2] = t.z; q[e4 * 4 + 3] = t.w;
    }
#pragma unroll
    for (int e = 0; e < 64; e++) o[e] = 0.f;

    float mrun = -1e30f;
    float lrun = 0.f;

    const uint8_t* mbase = mask + ((size_t)bb * L_ + r) * L_;
    const float* Kb = g_k + (bh * L_ << 6);
    const float* Vb = g_v + (bh * L_ << 6);

    for (int m0 = 0; m0 < L_; m0 += 64) {
        __syncthreads();
#pragma unroll
        for (int it = 0; it < 8; it++) {
            int f  = threadIdx.x + it * 128;  // float4 index in [0,1024)
            int j  = f >> 4;
            int e4 = f & 15;
            *(float4*)&Ks[j][e4 << 2] =
                *(const float4*)(Kb + ((size_t)(m0 + j) << 6) + (e4 << 2));
            *(float4*)&Vs[j][e4 << 2] =
                *(const float4*)(Vb + ((size_t)(m0 + j) << 6) + (e4 << 2));
        }
        __syncthreads();

        const uint8_t* mrow = mbase + m0;
#pragma unroll 2
        for (int j = 0; j < 64; j++) {
            float s = 0.f;
#pragma unroll
            for (int e = 0; e < 64; e++) s += q[e] * Ks[j][e];
            s *= 0.125f;                       // 1/sqrt(64)
            if (mrow[j]) s = -1e9f;

            if (s > mrun) {                    // rare rescale path
                float corr = __expf(mrun - s);
                lrun *= corr;
#pragma unroll
                for (int e = 0; e < 64; e++) o[e] *= corr;
                mrun = s;
            }
            float p = __expf(s - mrun);
            lrun += p;
#pragma unroll
            for (int e = 0; e < 64; e++) o[e] += p * Vs[j][e];
        }
    }

    float inv = 1.f / lrun;
    float* Out = g_o + ((bh * L_ + r) << 6);
#pragma unroll
    for (int e4 = 0; e4 < 16; e4++) {
        float4 t = make_float4(o[e4 * 4 + 0] * inv, o[e4 * 4 + 1] * inv,
                               o[e4 * 4 + 2] * inv, o[e4 * 4 + 3] * inv);
        *(float4*)(Out + (e4 << 2)) = t;
    }
}

// ---------------------------------------------------------------------------
// Kernel 3: output projection + residual.
// y[b,l,d] = x[b,l,d] + sum_{h,e} o[b,h,l,e] * w_o[h*64+e, d]
// GEMM M=4096, N=1024, K=1024. Tile 64x64, BK=16, 256 threads, 4x4 micro-tile.
// ---------------------------------------------------------------------------
__global__ __launch_bounds__(256) void oproj_kernel(
    const float* __restrict__ X, const float* __restrict__ Wo)
{
    const int m0 = blockIdx.x * 64;
    const int n0 = blockIdx.y * 64;

    __shared__ float As[16][68];
    __shared__ float Bs[16][64];

    const int tid = threadIdx.x;
    const int tx  = tid & 15;
    const int ty  = tid >> 4;
    const int lr  = tid >> 2;
    const int lc  = (tid & 3) << 2;

    const int row = m0 + lr;
    const int bb  = row >> 11;
    const int l   = row & (L_ - 1);

    float acc[4][4];
#pragma unroll
    for (int i = 0; i < 4; i++)
#pragma unroll
        for (int j = 0; j < 4; j++) acc[i][j] = 0.f;

    for (int k0 = 0; k0 < DM; k0 += 16) {
        int c  = k0 + lc;
        int hh = c >> 6;
        int e  = c & 63;
        float4 av = *(const float4*)(
            g_o + ((((size_t)bb * NH + hh) * L_ + l) << 6) + e);
        As[lc + 0][lr] = av.x;
        As[lc + 1][lr] = av.y;
        As[lc + 2][lr] = av.z;
        As[lc + 3][lr] = av.w;
        *(float4*)&Bs[ty][tx << 2] =
            *(const float4*)(Wo + (size_t)(k0 + ty) * DM + n0 + (tx << 2));
        __syncthreads();

#pragma unroll
        for (int kk = 0; kk < 16; kk++) {
            float4 a = *(float4*)&As[kk][ty << 2];
            float4 b = *(float4*)&Bs[kk][tx << 2];
            float av2[4] = {a.x, a.y, a.z, a.w};
            float bv2[4] = {b.x, b.y, b.z, b.w};
#pragma unroll
            for (int i = 0; i < 4; i++)
#pragma unroll
                for (int j = 0; j < 4; j++) acc[i][j] += av2[i] * bv2[j];
        }
        __syncthreads();
    }

#pragma unroll
    for (int i = 0; i < 4; i++) {
        int rrow = m0 + (ty << 2) + i;
        float4 xv = *(const float4*)(X + (size_t)rrow * DM + n0 + (tx << 2));
        float4 res = make_float4(acc[i][0] + xv.x, acc[i][1] + xv.y,
                                 acc[i][2] + xv.z, acc[i][3] + xv.w);
        *(float4*)(g_y + (size_t)rrow * DM + n0 + (tx << 2)) = res;
    }
}

// ---------------------------------------------------------------------------
// Kernel 4: LayerNorm, one block (256 threads) per row of 1024.
// ---------------------------------------------------------------------------
__global__ __launch_bounds__(256) void ln_kernel(
    const float* __restrict__ gamma, const float* __restrict__ beta,
    float* __restrict__ out)
{
    const int row = blockIdx.x;
    const int tid = threadIdx.x;
    const float* Y = g_y + (size_t)row * DM;

    float4 v = *(const float4*)(Y + (tid << 2));
    float s  = v.x + v.y + v.z + v.w;
    float sq = v.x * v.x + v.y * v.y + v.z * v.z + v.w * v.w;

#pragma unroll
    for (int off = 16; off > 0; off >>= 1) {
        s  += __shfl_xor_sync(0xffffffffu, s, off);
        sq += __shfl_xor_sync(0xffffffffu, sq, off);
    }

    __shared__ float red[18];
    const int wid = tid >> 5;
    if ((tid & 31) == 0) { red[wid] = s; red[wid + 8] = sq; }
    __syncthreads();
    if (tid == 0) {
        float ts = 0.f, tq = 0.f;
#pragma unroll
        for (int w = 0; w < 8; w++) { ts += red[w]; tq += red[w + 8]; }
        float mu  = ts * (1.f / DM);
        float var = tq * (1.f / DM) - mu * mu;
        red[16] = mu;
        red[17] = rsqrtf(var + 1e-5f);
    }
    __syncthreads();
    float mu   = red[16];
    float rstd = red[17];

    float4 g = *(const float4*)(gamma + (tid << 2));
    float4 b = *(const float4*)(beta  + (tid << 2));
    float4 res;
    res.x = (v.x - mu) * rstd * g.x + b.x;
    res.y = (v.y - mu) * rstd * g.y + b.y;
    res.z = (v.z - mu) * rstd * g.z + b.z;
    res.w = (v.w - mu) * rstd * g.w + b.w;
    *(float4*)(out + (size_t)row * DM + (tid << 2)) = res;
}

// ---------------------------------------------------------------------------
// Launch
// ---------------------------------------------------------------------------
extern "C" void kernel_launch(void* const* d_in, const int* in_sizes, int n_in,
                              void* d_out, int out_size)
{
    const float*   x     = (const float*)d_in[0];
    const uint8_t* mask  = (const uint8_t*)d_in[1];
    const float*   wq    = (const float*)d_in[2];
    const float*   wk    = (const float*)d_in[3];
    const float*   wv    = (const float*)d_in[4];
    const float*   wo    = (const float*)d_in[5];
    const float*   gamma = (const float*)d_in[6];
    const float*   beta  = (const float*)d_in[7];
    float*         out   = (float*)d_out;

    dim3 g1((B_ * L_) / 64, NH, 3);
    qkv_proj_kernel<<<g1, 256>>>(x, wq, wk, wv);

    dim3 g2(L_ / 128, NH, B_);
    attn_kernel<<<g2, 128>>>(mask);

    dim3 g3((B_ * L_) / 64, DM / 64);
    oproj_kernel<<<g3, 256>>>(x, wo);

    ln_kernel<<<B_ * L_, 256>>>(gamma, beta, out);
}

// round 4
// speedup vs baseline: 3.7845x; 3.7845x over previous
#include <cuda_runtime.h>
#include <cstdint>

#define B_  2
#define L_  2048
#define DM  1024
#define NH  16
#define DQ  64

// Scratch (allocation-free rule: __device__ globals)
__device__ float g_q[(size_t)B_ * NH * L_ * DQ];
__device__ float g_k[(size_t)B_ * NH * L_ * DQ];
__device__ float g_v[(size_t)B_ * NH * L_ * DQ];
__device__ float g_o[(size_t)B_ * NH * L_ * DQ];
__device__ float g_y[(size_t)B_ * L_ * DM];

__device__ __forceinline__ float to_tf32(float x) {
    asm("cvt.rna.tf32.f32 %0, %0;" : "+f"(x));
    return x;
}

__device__ __forceinline__ void mma8(float c[4], const uint32_t a[4], const uint32_t b[2]) {
    asm volatile(
        "mma.sync.aligned.m16n8k8.row.col.f32.tf32.tf32.f32 "
        "{%0,%1,%2,%3},{%4,%5,%6,%7},{%8,%9},{%0,%1,%2,%3};"
        : "+f"(c[0]), "+f"(c[1]), "+f"(c[2]), "+f"(c[3])
        : "r"(a[0]), "r"(a[1]), "r"(a[2]), "r"(a[3]), "r"(b[0]), "r"(b[1]));
}

// ---------------------------------------------------------------------------
// Kernel 1: fused QKV projection with tf32 MMA.
// Per (z, h): GEMM M=4096, N=64, K=1024. Block tile 128x64, BK=32.
// 8 warps in 4(m) x 2(n); warp tile 32x32 (2 m16-tiles x 4 n8-tiles).
// ---------------------------------------------------------------------------
__global__ __launch_bounds__(256) void qkv_kernel(
    const float* __restrict__ X,
    const float* __restrict__ Wq,
    const float* __restrict__ Wk,
    const float* __restrict__ Wv)
{
    __shared__ float As[128 * 36];   // A tile [m][k], stride 36 (bank-unique frags)
    __shared__ float Bs[64 * 36];    // B^T tile [n][k], stride 36

    const float* W;
    float* O;
    if (blockIdx.z == 0)      { W = Wq; O = g_q; }
    else if (blockIdx.z == 1) { W = Wk; O = g_k; }
    else                      { W = Wv; O = g_v; }

    const int h  = blockIdx.y;
    const int m0 = blockIdx.x * 128;
    const int tid  = threadIdx.x;
    const int lane = tid & 31;
    const int warp = tid >> 5;
    const int r4 = lane >> 2;
    const int gg = lane & 3;
    const int wm = warp & 3;
    const int wn = warp >> 2;

    const float* Wh = W + (size_t)h * DM * DQ;

    float acc[2][4][4];
#pragma unroll
    for (int i = 0; i < 2; i++)
#pragma unroll
        for (int j = 0; j < 4; j++)
#pragma unroll
            for (int t = 0; t < 4; t++) acc[i][j][t] = 0.f;

    const int eB  = tid & 63;
    const int kq0 = tid >> 6;

    for (int k0 = 0; k0 < DM; k0 += 32) {
        // A tile: 128x32, vectorized, converted to tf32
#pragma unroll
        for (int i = 0; i < 4; i++) {
            int f = tid + 256 * i;
            int m = f >> 3, kq = f & 7;
            float4 v = *(const float4*)(X + (size_t)(m0 + m) * DM + k0 + 4 * kq);
            v.x = to_tf32(v.x); v.y = to_tf32(v.y);
            v.z = to_tf32(v.z); v.w = to_tf32(v.w);
            *(float4*)&As[m * 36 + 4 * kq] = v;
        }
        // B^T tile: strided gmem reads, vector smem stores
#pragma unroll
        for (int p = 0; p < 2; p++) {
            int kq = kq0 + 4 * p;
            const float* src = Wh + (size_t)(k0 + 4 * kq) * DQ + eB;
            float4 v;
            v.x = to_tf32(src[0]);
            v.y = to_tf32(src[DQ]);
            v.z = to_tf32(src[2 * DQ]);
            v.w = to_tf32(src[3 * DQ]);
            *(float4*)&Bs[eB * 36 + 4 * kq] = v;
        }
        __syncthreads();

        const uint32_t* Au = (const uint32_t*)As;
        const uint32_t* Bu = (const uint32_t*)Bs;
#pragma unroll
        for (int ks = 0; ks < 4; ks++) {
            uint32_t a[2][4], b[4][2];
#pragma unroll
            for (int i = 0; i < 2; i++) {
                int row = 32 * wm + 16 * i + r4;
                int cb  = 8 * ks + gg;
                a[i][0] = Au[row * 36 + cb];
                a[i][1] = Au[(row + 8) * 36 + cb];
                a[i][2] = Au[row * 36 + cb + 4];
                a[i][3] = Au[(row + 8) * 36 + cb + 4];
            }
#pragma unroll
            for (int j = 0; j < 4; j++) {
                int col = 32 * wn + 8 * j + r4;
                b[j][0] = Bu[col * 36 + 8 * ks + gg];
                b[j][1] = Bu[col * 36 + 8 * ks + gg + 4];
            }
#pragma unroll
            for (int i = 0; i < 2; i++)
#pragma unroll
                for (int j = 0; j < 4; j++) mma8(acc[i][j], a[i], b[j]);
        }
        __syncthreads();
    }

#pragma unroll
    for (int i = 0; i < 2; i++) {
        int row = m0 + 32 * wm + 16 * i + r4;
        int b_  = row >> 11;
        int l   = row & (L_ - 1);
        float* base = O + ((((size_t)b_ * NH + h) * L_ + l) << 6);
#pragma unroll
        for (int j = 0; j < 4; j++) {
            int col = 32 * wn + 8 * j + 2 * gg;
            *(float2*)(base + col) = make_float2(acc[i][j][0], acc[i][j][1]);
            *(float2*)(base + (8 << 6) + col) = make_float2(acc[i][j][2], acc[i][j][3]);
        }
    }
}

// ---------------------------------------------------------------------------
// Kernel 2: flash attention with tf32 MMA.
// CTA = 128 query rows, 8 warps (16 rows each). Key tiles of 64.
// Dynamic smem: Qs[128][68] | Ks[64][68] | VTs[64][68] | Ps[128][68]
// ---------------------------------------------------------------------------
__global__ __launch_bounds__(256) void attn_kernel(const uint8_t* __restrict__ mask)
{
    extern __shared__ float sm[];
    float* Qs  = sm;                    // [128][68]
    float* Ks  = Qs + 128 * 68;         // [64][68]
    float* VTs = Ks + 64 * 68;          // [64][68] (e-major, key minor)
    float* Ps  = VTs + 64 * 68;         // [128][68]

    const int tid  = threadIdx.x;
    const int lane = tid & 31;
    const int warp = tid >> 5;
    const int r4 = lane >> 2;
    const int gg = lane & 3;
    const int h  = blockIdx.y;
    const int bb = blockIdx.z;
    const int m0 = blockIdx.x * 128;
    const size_t bh = (size_t)bb * NH + h;

    const float* Qg = g_q + ((bh * L_ + m0) << 6);
    const float* Kg = g_k + ((bh * L_) << 6);
    const float* Vg = g_v + ((bh * L_) << 6);
    const uint8_t* Mg = mask + ((size_t)bb * L_ + m0) * L_;

    // Stage Q (converted to tf32)
#pragma unroll
    for (int i = 0; i < 8; i++) {
        int f = tid + 256 * i;
        int row = f >> 4, eq = f & 15;
        float4 v = *(const float4*)(Qg + ((size_t)row << 6) + 4 * eq);
        v.x = to_tf32(v.x); v.y = to_tf32(v.y);
        v.z = to_tf32(v.z); v.w = to_tf32(v.w);
        *(float4*)&Qs[row * 68 + 4 * eq] = v;
    }
    __syncthreads();

    const int wq = warp * 16;
    float cO[8][4];
#pragma unroll
    for (int j = 0; j < 8; j++)
#pragma unroll
        for (int t = 0; t < 4; t++) cO[j][t] = 0.f;
    float mrow[2] = {-1e30f, -1e30f};
    float lrow[2] = {0.f, 0.f};

    const int eV  = tid & 63;
    const int kqV = tid >> 6;

    for (int kb = 0; kb < L_; kb += 64) {
        __syncthreads();
        // K tile
#pragma unroll
        for (int i = 0; i < 4; i++) {
            int f = tid + 256 * i;
            int row = f >> 4, eq = f & 15;
            float4 v = *(const float4*)(Kg + ((size_t)(kb + row) << 6) + 4 * eq);
            v.x = to_tf32(v.x); v.y = to_tf32(v.y);
            v.z = to_tf32(v.z); v.w = to_tf32(v.w);
            *(float4*)&Ks[row * 68 + 4 * eq] = v;
        }
        // V^T tile
#pragma unroll
        for (int p = 0; p < 4; p++) {
            int kq = kqV + 4 * p;
            const float* src = Vg + ((size_t)(kb + 4 * kq) << 6) + eV;
            float4 v;
            v.x = to_tf32(src[0]);
            v.y = to_tf32(src[64]);
            v.z = to_tf32(src[128]);
            v.w = to_tf32(src[192]);
            *(float4*)&VTs[eV * 68 + 4 * kq] = v;
        }
        // mask OR-check (fast path: all false)
        unsigned any = 0;
#pragma unroll
        for (int i = 0; i < 2; i++) {
            int f = tid + 256 * i;
            int row = f >> 2, q16 = f & 3;
            uint4 mv = *(const uint4*)(Mg + (size_t)row * L_ + kb + 16 * q16);
            any |= (mv.x | mv.y | mv.z | mv.w);
        }
        int flag = __syncthreads_or((int)(any != 0));

        // S = Q K^T
        float cS[8][4];
#pragma unroll
        for (int j = 0; j < 8; j++)
#pragma unroll
            for (int t = 0; t < 4; t++) cS[j][t] = 0.f;

        const uint32_t* Qu = (const uint32_t*)Qs;
        const uint32_t* Ku = (const uint32_t*)Ks;
#pragma unroll
        for (int ks = 0; ks < 8; ks++) {
            uint32_t a[4];
            int cb = 8 * ks + gg;
            a[0] = Qu[(wq + r4) * 68 + cb];
            a[1] = Qu[(wq + r4 + 8) * 68 + cb];
            a[2] = Qu[(wq + r4) * 68 + cb + 4];
            a[3] = Qu[(wq + r4 + 8) * 68 + cb + 4];
#pragma unroll
            for (int j = 0; j < 8; j++) {
                uint32_t b[2];
                b[0] = Ku[(8 * j + r4) * 68 + cb];
                b[1] = Ku[(8 * j + r4) * 68 + cb + 4];
                mma8(cS[j], a, b);
            }
        }
        // scale
#pragma unroll
        for (int j = 0; j < 8; j++)
#pragma unroll
            for (int t = 0; t < 4; t++) cS[j][t] *= 0.125f;
        // mask (rare path)
        if (flag) {
#pragma unroll
            for (int j = 0; j < 8; j++) {
                int col = kb + 8 * j + 2 * gg;
                const uint8_t* mlo = Mg + (size_t)(wq + r4) * L_ + col;
                const uint8_t* mhi = Mg + (size_t)(wq + r4 + 8) * L_ + col;
                if (mlo[0]) cS[j][0] = -1e9f;
                if (mlo[1]) cS[j][1] = -1e9f;
                if (mhi[0]) cS[j][2] = -1e9f;
                if (mhi[1]) cS[j][3] = -1e9f;
            }
        }
        // online softmax (per half: rows r4 and r4+8)
#pragma unroll
        for (int hh = 0; hh < 2; hh++) {
            float mx = -1e30f;
#pragma unroll
            for (int j = 0; j < 8; j++)
                mx = fmaxf(mx, fmaxf(cS[j][2 * hh], cS[j][2 * hh + 1]));
            mx = fmaxf(mx, __shfl_xor_sync(0xffffffffu, mx, 1));
            mx = fmaxf(mx, __shfl_xor_sync(0xffffffffu, mx, 2));
            float newm = fmaxf(mrow[hh], mx);
            float corr = __expf(mrow[hh] - newm);
            mrow[hh] = newm;
            float sum = 0.f;
#pragma unroll
            for (int j = 0; j < 8; j++) {
                float p0 = __expf(cS[j][2 * hh] - newm);
                float p1 = __expf(cS[j][2 * hh + 1] - newm);
                cS[j][2 * hh] = p0;
                cS[j][2 * hh + 1] = p1;
                sum += p0 + p1;
            }
            sum += __shfl_xor_sync(0xffffffffu, sum, 1);
            sum += __shfl_xor_sync(0xffffffffu, sum, 2);
            lrow[hh] = lrow[hh] * corr + sum;
#pragma unroll
            for (int j = 0; j < 8; j++) {
                cO[j][2 * hh] *= corr;
                cO[j][2 * hh + 1] *= corr;
            }
        }
        // store P (tf32) to this warp's rows of Ps
#pragma unroll
        for (int j = 0; j < 8; j++) {
            *(float2*)&Ps[(wq + r4) * 68 + 8 * j + 2 * gg] =
                make_float2(to_tf32(cS[j][0]), to_tf32(cS[j][1]));
            *(float2*)&Ps[(wq + r4 + 8) * 68 + 8 * j + 2 * gg] =
                make_float2(to_tf32(cS[j][2]), to_tf32(cS[j][3]));
        }
        __syncwarp();

        // O += P V
        const uint32_t* Pu = (const uint32_t*)Ps;
        const uint32_t* Vu = (const uint32_t*)VTs;
#pragma unroll
        for (int ks = 0; ks < 8; ks++) {
            uint32_t a[4];
            int cb = 8 * ks + gg;
            a[0] = Pu[(wq + r4) * 68 + cb];
            a[1] = Pu[(wq + r4 + 8) * 68 + cb];
            a[2] = Pu[(wq + r4) * 68 + cb + 4];
            a[3] = Pu[(wq + r4 + 8) * 68 + cb + 4];
#pragma unroll
            for (int j = 0; j < 8; j++) {
                uint32_t b[2];
                b[0] = Vu[(8 * j + r4) * 68 + cb];
                b[1] = Vu[(8 * j + r4) * 68 + cb + 4];
                mma8(cO[j], a, b);
            }
        }
    }

    // epilogue
    float inv0 = 1.f / lrow[0];
    float inv1 = 1.f / lrow[1];
    float* Ob = g_o + ((bh * L_ + m0 + wq) << 6);
#pragma unroll
    for (int j = 0; j < 8; j++) {
        int col = 8 * j + 2 * gg;
        *(float2*)(Ob + ((size_t)r4 << 6) + col) =
            make_float2(cO[j][0] * inv0, cO[j][1] * inv0);
        *(float2*)(Ob + ((size_t)(r4 + 8) << 6) + col) =
            make_float2(cO[j][2] * inv1, cO[j][3] * inv1);
    }
}

// ---------------------------------------------------------------------------
// Kernel 3: output projection + residual with tf32 MMA.
// GEMM M=4096, N=1024, K=1024. Block tile 128x64, BK=32.
// ---------------------------------------------------------------------------
__global__ __launch_bounds__(256) void oproj_kernel(
    const float* __restrict__ X, const float* __restrict__ Wo)
{
    __shared__ float As[128 * 36];
    __shared__ float Bs[64 * 36];

    const int m0 = blockIdx.x * 128;
    const int n0 = blockIdx.y * 64;
    const int tid  = threadIdx.x;
    const int lane = tid & 31;
    const int warp = tid >> 5;
    const int r4 = lane >> 2;
    const int gg = lane & 3;
    const int wm = warp & 3;
    const int wn = warp >> 2;

    float acc[2][4][4];
#pragma unroll
    for (int i = 0; i < 2; i++)
#pragma unroll
        for (int j = 0; j < 4; j++)
#pragma unroll
            for (int t = 0; t < 4; t++) acc[i][j][t] = 0.f;

    const int eB  = tid & 63;
    const int kq0 = tid >> 6;

    for (int k0 = 0; k0 < DM; k0 += 32) {
        // A tile from g_o ([b][h][l][e] with k = h*64+e; BK chunk stays in one head)
#pragma unroll
        for (int i = 0; i < 4; i++) {
            int f = tid + 256 * i;
            int m = f >> 3, kq = f & 7;
            int row = m0 + m;
            int b_ = row >> 11, l = row & (L_ - 1);
            int k  = k0 + 4 * kq;
            int hk = k >> 6, ek = k & 63;
            float4 v = *(const float4*)(
                g_o + ((((size_t)b_ * NH + hk) * L_ + l) << 6) + ek);
            v.x = to_tf32(v.x); v.y = to_tf32(v.y);
            v.z = to_tf32(v.z); v.w = to_tf32(v.w);
            *(float4*)&As[m * 36 + 4 * kq] = v;
        }
#pragma unroll
        for (int p = 0; p < 2; p++) {
            int kq = kq0 + 4 * p;
            const float* src = Wo + (size_t)(k0 + 4 * kq) * DM + n0 + eB;
            float4 v;
            v.x = to_tf32(src[0]);
            v.y = to_tf32(src[DM]);
            v.z = to_tf32(src[2 * DM]);
            v.w = to_tf32(src[3 * DM]);
            *(float4*)&Bs[eB * 36 + 4 * kq] = v;
        }
        __syncthreads();

        const uint32_t* Au = (const uint32_t*)As;
        const uint32_t* Bu = (const uint32_t*)Bs;
#pragma unroll
        for (int ks = 0; ks < 4; ks++) {
            uint32_t a[2][4], b[4][2];
#pragma unroll
            for (int i = 0; i < 2; i++) {
                int row = 32 * wm + 16 * i + r4;
                int cb  = 8 * ks + gg;
                a[i][0] = Au[row * 36 + cb];
                a[i][1] = Au[(row + 8) * 36 + cb];
                a[i][2] = Au[row * 36 + cb + 4];
                a[i][3] = Au[(row + 8) * 36 + cb + 4];
            }
#pragma unroll
            for (int j = 0; j < 4; j++) {
                int col = 32 * wn + 8 * j + r4;
                b[j][0] = Bu[col * 36 + 8 * ks + gg];
                b[j][1] = Bu[col * 36 + 8 * ks + gg + 4];
            }
#pragma unroll
            for (int i = 0; i < 2; i++)
#pragma unroll
                for (int j = 0; j < 4; j++) mma8(acc[i][j], a[i], b[j]);
        }
        __syncthreads();
    }

    // epilogue: add residual X, write g_y
#pragma unroll
    for (int i = 0; i < 2; i++) {
        int row = m0 + 32 * wm + 16 * i + r4;
#pragma unroll
        for (int j = 0; j < 4; j++) {
            int col = n0 + 32 * wn + 8 * j + 2 * gg;
            float2 x0 = *(const float2*)(X + (size_t)row * DM + col);
            float2 x1 = *(const float2*)(X + (size_t)(row + 8) * DM + col);
            *(float2*)(g_y + (size_t)row * DM + col) =
                make_float2(acc[i][j][0] + x0.x, acc[i][j][1] + x0.y);
            *(float2*)(g_y + (size_t)(row + 8) * DM + col) =
                make_float2(acc[i][j][2] + x1.x, acc[i][j][3] + x1.y);
        }
    }
}

// ---------------------------------------------------------------------------
// Kernel 4: LayerNorm, one block (256 threads) per row of 1024.
// ---------------------------------------------------------------------------
__global__ __launch_bounds__(256) void ln_kernel(
    const float* __restrict__ gamma, const float* __restrict__ beta,
    float* __restrict__ out)
{
    const int row = blockIdx.x;
    const int tid = threadIdx.x;
    const float* Y = g_y + (size_t)row * DM;

    float4 v = *(const float4*)(Y + (tid << 2));
    float s  = v.x + v.y + v.z + v.w;
    float sq = v.x * v.x + v.y * v.y + v.z * v.z + v.w * v.w;

#pragma unroll
    for (int off = 16; off > 0; off >>= 1) {
        s  += __shfl_xor_sync(0xffffffffu, s, off);
        sq += __shfl_xor_sync(0xffffffffu, sq, off);
    }

    __shared__ float red[18];
    const int wid = tid >> 5;
    if ((tid & 31) == 0) { red[wid] = s; red[wid + 8] = sq; }
    __syncthreads();
    if (tid == 0) {
        float ts = 0.f, tq = 0.f;
#pragma unroll
        for (int w = 0; w < 8; w++) { ts += red[w]; tq += red[w + 8]; }
        float mu  = ts * (1.f / DM);
        float var = tq * (1.f / DM) - mu * mu;
        red[16] = mu;
        red[17] = rsqrtf(var + 1e-5f);
    }
    __syncthreads();
    float mu   = red[16];
    float rstd = red[17];

    float4 g = *(const float4*)(gamma + (tid << 2));
    float4 b = *(const float4*)(beta  + (tid << 2));
    float4 res;
    res.x = (v.x - mu) * rstd * g.x + b.x;
    res.y = (v.y - mu) * rstd * g.y + b.y;
    res.z = (v.z - mu) * rstd * g.z + b.z;
    res.w = (v.w - mu) * rstd * g.w + b.w;
    *(float4*)(out + (size_t)row * DM + (tid << 2)) = res;
}

// ---------------------------------------------------------------------------
// Launch
// ---------------------------------------------------------------------------
extern "C" void kernel_launch(void* const* d_in, const int* in_sizes, int n_in,
                              void* d_out, int out_size)
{
    const float*   x     = (const float*)d_in[0];
    const uint8_t* mask  = (const uint8_t*)d_in[1];
    const float*   wq    = (const float*)d_in[2];
    const float*   wk    = (const float*)d_in[3];
    const float*   wv    = (const float*)d_in[4];
    const float*   wo    = (const float*)d_in[5];
    const float*   gamma = (const float*)d_in[6];
    const float*   beta  = (const float*)d_in[7];
    float*         out   = (float*)d_out;

    const int attn_smem = (128 * 68 + 64 * 68 + 64 * 68 + 128 * 68) * 4; // 104448
    cudaFuncSetAttribute(attn_kernel,
                         cudaFuncAttributeMaxDynamicSharedMemorySize, attn_smem);

    dim3 g1((B_ * L_) / 128, NH, 3);
    qkv_kernel<<<g1, 256>>>(x, wq, wk, wv);

    dim3 g2(L_ / 128, NH, B_);
    attn_kernel<<<g2, 256, attn_smem>>>(mask);

    dim3 g3((B_ * L_) / 128, DM / 64);
    oproj_kernel<<<g3, 256>>>(x, wo);

    ln_kernel<<<B_ * L_, 256>>>(gamma, beta, out);
}